// round 3
// baseline (speedup 1.0000x reference)
#include <cuda_runtime.h>
#include <cstdint>
#include <cstddef>

#define BB 4
#define NN 4096
#define DD 256
#define RR 64
#define KK 16

#define FMA2(d, a, b) asm("fma.rn.f32x2 %0, %1, %2, %0;" : "+l"(d) : "l"(a), "l"(b))

// ---------------- device scratch (static; no runtime allocation) ----------------
__device__ float g_scores[(size_t)BB * NN * NN];     // 256 MB
__device__ float g_sp[(size_t)BB * NN * RR];
__device__ float g_dp[(size_t)BB * NN * RR];
__device__ float g_w[(size_t)BB * NN * KK];
__device__ int   g_idx[(size_t)BB * NN * KK];
__device__ float g_kstate[NN];
__device__ float g_kval[(size_t)NN * DD];
__device__ float g_nk[(size_t)NN * DD];
__device__ float g_nv[(size_t)BB * NN * DD];
__device__ float g_nb[(size_t)BB * NN * DD];
__device__ float g_ds[(size_t)BB * NN];

// ---------------- reductions ----------------
__device__ __forceinline__ float warpSum(float v) {
#pragma unroll
    for (int o = 16; o > 0; o >>= 1) v += __shfl_xor_sync(0xffffffffu, v, o);
    return v;
}
__device__ __forceinline__ float warpMax(float v) {
#pragma unroll
    for (int o = 16; o > 0; o >>= 1) v = fmaxf(v, __shfl_xor_sync(0xffffffffu, v, o));
    return v;
}
__device__ __forceinline__ float blockSum256(float v) {
    __shared__ float sh[8];
    int wid = threadIdx.x >> 5, lid = threadIdx.x & 31;
    v = warpSum(v);
    if (lid == 0) sh[wid] = v;
    __syncthreads();
    float r = sh[0] + sh[1] + sh[2] + sh[3] + sh[4] + sh[5] + sh[6] + sh[7];
    __syncthreads();
    return r;
}
__device__ __forceinline__ float blockMax256(float v) {
    __shared__ float sh[8];
    int wid = threadIdx.x >> 5, lid = threadIdx.x & 31;
    v = warpMax(v);
    if (lid == 0) sh[wid] = v;
    __syncthreads();
    float r = fmaxf(fmaxf(fmaxf(sh[0], sh[1]), fmaxf(sh[2], sh[3])),
                    fmaxf(fmaxf(sh[4], sh[5]), fmaxf(sh[6], sh[7])));
    __syncthreads();
    return r;
}

// ---------------- layernorm over rows of 256 ----------------
__global__ void __launch_bounds__(256) ln_kernel(const float* __restrict__ x, int srcMod,
                                                 const float* __restrict__ res,
                                                 const float* __restrict__ g,
                                                 const float* __restrict__ bt,
                                                 float* __restrict__ out) {
    int row = blockIdx.x;
    int srow = srcMod ? (row & (srcMod - 1)) : row;
    int t = threadIdx.x;
    float v = x[(size_t)srow * DD + t];
    if (res) v += res[(size_t)row * DD + t];
    float mean = blockSum256(v) * (1.f / DD);
    float d = v - mean;
    float var = blockSum256(d * d) * (1.f / DD);
    out[(size_t)row * DD + t] = d * rsqrtf(var + 1e-5f) * g[t] + bt[t];
}

// ---------------- signed softmax over rows of 4096 ----------------
__global__ void __launch_bounds__(256) ss_kernel(const float* __restrict__ x, int xB,
                                                 const float* __restrict__ add,
                                                 float* __restrict__ out) {
    int b = blockIdx.x;
    const float* xr = x + (xB ? 0 : (size_t)b * NN);
    const float* ar = add ? add + (size_t)b * NN : nullptr;
    int t = threadIdx.x;
    float v[16];
    float mx = 0.f;
#pragma unroll
    for (int i = 0; i < 16; i++) {
        float u = xr[t + 256 * i];
        if (ar) u += ar[t + 256 * i];
        v[i] = u;
        mx = fmaxf(mx, fabsf(u));
    }
    mx = blockMax256(mx);
    float s = 0.f;
#pragma unroll
    for (int i = 0; i < 16; i++) s += expf(fabsf(v[i]) - mx);
    s = blockSum256(s);
    float inv = 1.f / s;
#pragma unroll
    for (int i = 0; i < 16; i++) {
        float u = v[i];
        float sg = (u > 0.f) ? 1.f : ((u < 0.f) ? -1.f : 0.f);
        out[(size_t)b * NN + t + 256 * i] = sg * expf(fabsf(u) - mx) * inv;
    }
}

// ---------------- projection v3: X[rows,256] @ W[256,64] ----------------
// 256 threads, 64 rows/block, 4 threads/row (16 cols each), W chunks in smem.
__global__ void __launch_bounds__(256) proj_kernel(const float* __restrict__ X,
                                                   const float* __restrict__ W,
                                                   float* __restrict__ out, int nrows) {
    __shared__ float Ws[128][64];
    int t = threadIdx.x;
    int r = blockIdx.x * 64 + (t >> 2);
    int q = t & 3;                       // col group: cols q*16 .. q*16+15
    unsigned long long acc[8];
#pragma unroll
    for (int i = 0; i < 8; i++) acc[i] = 0ull;

    for (int ch = 0; ch < 2; ch++) {
        __syncthreads();
#pragma unroll
        for (int i = 0; i < 8; i++) {
            int idx = t * 8 + i;
            int d = idx >> 4, c4 = idx & 15;
            *(float4*)&Ws[d][c4 * 4] = *(const float4*)&W[(size_t)(ch * 128 + d) * RR + c4 * 4];
        }
        __syncthreads();
        const float4* Xr = (const float4*)(X + (size_t)r * DD + ch * 128);
#pragma unroll 4
        for (int d4 = 0; d4 < 32; d4++) {
            float4 xv = Xr[d4];
            float xs[4] = {xv.x, xv.y, xv.z, xv.w};
#pragma unroll
            for (int u = 0; u < 4; u++) {
                unsigned long long xd;
                asm("mov.b64 %0, {%1, %1};" : "=l"(xd) : "r"(__float_as_uint(xs[u])));
                const ulonglong2* wr = (const ulonglong2*)&Ws[d4 * 4 + u][q * 16];
#pragma unroll
                for (int jp = 0; jp < 4; jp++) {
                    ulonglong2 wv = wr[jp];
                    FMA2(acc[jp * 2], xd, wv.x);
                    FMA2(acc[jp * 2 + 1], xd, wv.y);
                }
            }
        }
    }
    float2* o = (float2*)(out + (size_t)r * RR + q * 16);
#pragma unroll
    for (int i = 0; i < 8; i++) o[i] = *(float2*)&acc[i];
}

// ---------------- score GEMM (f32x2, duplicated-A smem) ----------------
__global__ void __launch_bounds__(256) score_gemm_kernel(const float* __restrict__ dp,
                                                         const float* __restrict__ sp,
                                                         float* __restrict__ out,
                                                         int dpB, int spB) {
    __shared__ float sD[32][264];   // A duplicated: row r at cols 2r, 2r+1 (+pad)
    __shared__ float sS[32][132];
    int b = blockIdx.z;
    int n0 = blockIdx.y * 128;
    int m0 = blockIdx.x * 128;
    const float* dpb = dp + (dpB ? 0 : (size_t)b * NN * RR);
    const float* spb = sp + (spB ? 0 : (size_t)b * NN * RR);
    int t = threadIdx.x;
    int tx = t & 15, ty = t >> 4;
    unsigned long long acc[8][4];
#pragma unroll
    for (int i = 0; i < 8; i++)
#pragma unroll
        for (int j = 0; j < 4; j++) acc[i][j] = 0ull;

    for (int kc = 0; kc < 2; kc++) {
        __syncthreads();
#pragma unroll
        for (int i = 0; i < 4; i++) {
            int s = t + i * 256;       // 0..1023
            int r = s >> 3;            // row 0..127
            int kq = s & 7;            // float4 group within 32-k chunk
            float4 dv = *(const float4*)(dpb + (size_t)(n0 + r) * RR + kc * 32 + kq * 4);
            float2 p;
            p.x = p.y = dv.x; *(float2*)&sD[kq * 4 + 0][2 * r] = p;
            p.x = p.y = dv.y; *(float2*)&sD[kq * 4 + 1][2 * r] = p;
            p.x = p.y = dv.z; *(float2*)&sD[kq * 4 + 2][2 * r] = p;
            p.x = p.y = dv.w; *(float2*)&sD[kq * 4 + 3][2 * r] = p;
            float4 sv = *(const float4*)(spb + (size_t)(m0 + r) * RR + kc * 32 + kq * 4);
            sS[kq * 4 + 0][r] = sv.x; sS[kq * 4 + 1][r] = sv.y;
            sS[kq * 4 + 2][r] = sv.z; sS[kq * 4 + 3][r] = sv.w;
        }
        __syncthreads();
#pragma unroll 4
        for (int k = 0; k < 32; k++) {
            ulonglong2 A0 = *(const ulonglong2*)&sD[k][ty * 8];        // dup rows ty*4, ty*4+1
            ulonglong2 A1 = *(const ulonglong2*)&sD[k][ty * 8 + 4];    // rows ty*4+2, +3
            ulonglong2 A2 = *(const ulonglong2*)&sD[k][128 + ty * 8];  // rows 64+ty*4, +1
            ulonglong2 A3 = *(const ulonglong2*)&sD[k][128 + ty * 8 + 4];
            ulonglong2 B0 = *(const ulonglong2*)&sS[k][tx * 4];
            ulonglong2 B1 = *(const ulonglong2*)&sS[k][64 + tx * 4];
            unsigned long long ad[8] = {A0.x, A0.y, A1.x, A1.y, A2.x, A2.y, A3.x, A3.y};
#pragma unroll
            for (int i = 0; i < 8; i++) {
                FMA2(acc[i][0], ad[i], B0.x);
                FMA2(acc[i][1], ad[i], B0.y);
                FMA2(acc[i][2], ad[i], B1.x);
                FMA2(acc[i][3], ad[i], B1.y);
            }
        }
    }
    float* outb = out + ((size_t)b * NN + n0) * NN + m0;
#pragma unroll
    for (int i = 0; i < 8; i++) {
        int n = (i < 4) ? (ty * 4 + i) : (64 + ty * 4 + (i - 4));
        float2 c0 = *(float2*)&acc[i][0];
        float2 c1 = *(float2*)&acc[i][1];
        float2 c2 = *(float2*)&acc[i][2];
        float2 c3 = *(float2*)&acc[i][3];
        float4 r0 = make_float4(c0.x * 0.125f, c0.y * 0.125f, c1.x * 0.125f, c1.y * 0.125f);
        float4 r1 = make_float4(c2.x * 0.125f, c2.y * 0.125f, c3.x * 0.125f, c3.y * 0.125f);
        *(float4*)(outb + (size_t)n * NN + tx * 4) = r0;
        *(float4*)(outb + (size_t)n * NN + 64 + tx * 4) = r1;
    }
}

// ---------------- top-16 by |score| per row: threshold + rank selection ----------------
__global__ void __launch_bounds__(256) topk_kernel(const float* __restrict__ scores,
                                                   float* __restrict__ wOut,
                                                   int* __restrict__ idxOut) {
    __shared__ unsigned int sVal[256];
    __shared__ int sColA[256];
    __shared__ unsigned int warp2[8];
    __shared__ int sCnt;
    size_t row = blockIdx.x;
    const float* sr = scores + row * (size_t)NN;
    int t = threadIdx.x;
    int lid = t & 31, wid = t >> 5;

    float vv[16];
    unsigned int kk[16];
#pragma unroll
    for (int i = 0; i < 4; i++) {
        float4 v = *(const float4*)&sr[t * 4 + i * 1024];
        vv[i * 4 + 0] = v.x; vv[i * 4 + 1] = v.y; vv[i * 4 + 2] = v.z; vv[i * 4 + 3] = v.w;
    }
#pragma unroll
    for (int e = 0; e < 16; e++) kk[e] = __float_as_uint(vv[e]) & 0x7fffffffu;

    unsigned int m1 = 0u, m2 = 0u;
#pragma unroll
    for (int e = 0; e < 16; e++) {
        unsigned int k = kk[e];
        if (k > m1) { m2 = m1; m1 = k; }
        else if (k > m2) { m2 = k; }
    }
#pragma unroll
    for (int o = 16; o > 0; o >>= 1) {
        unsigned int o1 = __shfl_xor_sync(0xffffffffu, m1, o);
        unsigned int o2 = __shfl_xor_sync(0xffffffffu, m2, o);
        if (o1 > m1) { m2 = (m1 > o2) ? m1 : o2; m1 = o1; }
        else { m2 = (m2 > o1) ? m2 : o1; }
    }
    if (lid == 0) warp2[wid] = m2;
    if (t == 0) sCnt = 0;
    __syncthreads();
    unsigned int T = warp2[0];
#pragma unroll
    for (int u = 1; u < 8; u++) T = (warp2[u] < T) ? warp2[u] : T;

#pragma unroll
    for (int e = 0; e < 16; e++) {
        if (kk[e] >= T) {
            int p = atomicAdd(&sCnt, 1);
            if (p < 256) {
                sVal[p] = __float_as_uint(vv[e]);
                sColA[p] = t * 4 + (e & 3) + (e >> 2) * 1024;
            }
        }
    }
    __syncthreads();
    int C = sCnt;
    if (C <= 256) {
        if (t < C) {
            unsigned int vb = sVal[t];
            unsigned int ki = vb & 0x7fffffffu;
            int ci = sColA[t];
            int rank = 0;
            for (int j = 0; j < C; j++) {
                unsigned int vj = sVal[j];
                unsigned int kj = vj & 0x7fffffffu;
                int cj = sColA[j];
                rank += (kj > ki) || (kj == ki && cj < ci);
            }
            if (rank < KK) {
                wOut[row * KK + rank] = __uint_as_float(vb);
                idxOut[row * KK + rank] = ci;
            }
        }
    } else if (t == 0) {
        unsigned int bk[16]; float bv[16]; int bc[16];
        int cnt = 0;
        for (int c = 0; c < NN; c++) {
            float val = sr[c];
            unsigned int key = __float_as_uint(val) & 0x7fffffffu;
            if (cnt == 16 && key <= bk[15]) continue;
            int pos = (cnt < 16) ? cnt : 15;
            while (pos > 0 && bk[pos - 1] < key) {
                bk[pos] = bk[pos - 1]; bv[pos] = bv[pos - 1]; bc[pos] = bc[pos - 1];
                pos--;
            }
            bk[pos] = key; bv[pos] = val; bc[pos] = c;
            if (cnt < 16) cnt++;
        }
        for (int k = 0; k < KK; k++) {
            wOut[row * KK + k] = bv[k];
            idxOut[row * KK + k] = bc[k];
        }
    }
}

// ---------------- fused message aggregation + optional residual layernorm ----------------
// If g != nullptr: outVal[row] = LN(res[srow] + dval) with gain g / bias bt.
// Else: outVal[row] = dval.
__global__ void __launch_bounds__(256) msg_kernel(const float* __restrict__ w,
                                                  const int* __restrict__ idx,
                                                  const float* __restrict__ srcval, int srcB,
                                                  const float* __restrict__ state,
                                                  const float* __restrict__ res, int resMod,
                                                  const float* __restrict__ g,
                                                  const float* __restrict__ bt,
                                                  float* __restrict__ outVal,
                                                  float* __restrict__ dstate) {
    __shared__ float sW[16];
    __shared__ int sI[16];
    __shared__ float sNorm[16];
    size_t row = blockIdx.x;
    int b = (int)(row >> 12);
    int t = threadIdx.x;
    if (t < 16) { sW[t] = w[row * KK + t]; sI[t] = idx[row * KK + t]; }
    __syncthreads();
    if (t == 0) {
        float mx = 0.f;
        for (int k = 0; k < 16; k++) mx = fmaxf(mx, fabsf(sW[k]));
        float e[16];
        float s = 0.f;
        for (int k = 0; k < 16; k++) { e[k] = expf(fabsf(sW[k]) - mx); s += e[k]; }
        float inv = 1.f / s;
        float dsum = 0.f;
        for (int k = 0; k < 16; k++) {
            float u = sW[k];
            float sg = (u > 0.f) ? 1.f : ((u < 0.f) ? -1.f : 0.f);
            float wt = sg * e[k] * inv;
            if (state) {
                float st = state[(size_t)b * NN + sI[k]];
                float sp = fmaxf(st, 0.f) + log1pf(expf(-fabsf(st)));  // softplus
                wt *= sp;
            }
            sW[k] = wt;
            dsum += wt;
        }
        dstate[row] = dsum;
    }
    __syncthreads();
    const float* base = srcval + (srcB ? 0 : (size_t)b * NN * DD);
    int wid = t >> 5, lid = t & 31;
    for (int k = wid; k < 16; k += 8) {
        const float* v = base + (size_t)sI[k] * DD;
        float ss = 0.f;
#pragma unroll
        for (int i = lid; i < 256; i += 32) { float x = v[i]; ss += x * x; }
        ss = warpSum(ss);
        if (lid == 0) sNorm[k] = sqrtf(ss) + 1e-6f;
    }
    __syncthreads();
    float acc = 0.f;
#pragma unroll
    for (int k = 0; k < 16; k++) {
        const float* v = base + (size_t)sI[k] * DD;
        acc = fmaf(sW[k] / sNorm[k], v[t], acc);
    }
    if (g) {
        int srow = resMod ? (int)(row & (resMod - 1)) : (int)row;
        float v = res[(size_t)srow * DD + t] + acc;
        float mean = blockSum256(v) * (1.f / DD);
        float d = v - mean;
        float var = blockSum256(d * d) * (1.f / DD);
        outVal[row * (size_t)DD + t] = d * rsqrtf(var + 1e-5f) * g[t] + bt[t];
    } else {
        outVal[row * (size_t)DD + t] = acc;
    }
}

// ---------------- host orchestration ----------------
extern "C" void kernel_launch(void* const* d_in, const int* in_sizes, int n_in,
                              void* d_out, int out_size) {
    const float* b_state    = (const float*)d_in[0];
    const float* b_val      = (const float*)d_in[1];
    const float* init_state = (const float*)d_in[2];
    const float* init_val   = (const float*)d_in[3];
    const float* U_bk = (const float*)d_in[4];
    const float* V_bk = (const float*)d_in[5];
    const float* U_kb = (const float*)d_in[6];
    const float* V_kb = (const float*)d_in[7];
    const float* U_p  = (const float*)d_in[8];
    const float* V_p  = (const float*)d_in[9];
    const float* kn_g = (const float*)d_in[10];
    const float* kn_b = (const float*)d_in[11];
    const float* bn_g = (const float*)d_in[12];
    const float* bn_b = (const float*)d_in[13];
    const float* pn_g = (const float*)d_in[14];
    const float* pn_b = (const float*)d_in[15];

    float* out = (float*)d_out;
    float* o_rstate = out;
    float* o_rval   = o_rstate + (size_t)BB * NN;
    float* o_pstate = o_rval + (size_t)BB * NN * DD;
    float* o_pval   = o_pstate + (size_t)BB * NN;
    float* o_bds    = o_pval + (size_t)BB * NN * DD;
    float* o_bdv    = o_bds + (size_t)BB * NN;

    float *p_scores, *p_sp, *p_dp, *p_w, *p_kstate, *p_kval, *p_nk, *p_nv, *p_nb, *p_ds;
    int* p_idx;
    cudaGetSymbolAddress((void**)&p_scores, g_scores);
    cudaGetSymbolAddress((void**)&p_sp, g_sp);
    cudaGetSymbolAddress((void**)&p_dp, g_dp);
    cudaGetSymbolAddress((void**)&p_w, g_w);
    cudaGetSymbolAddress((void**)&p_idx, g_idx);
    cudaGetSymbolAddress((void**)&p_kstate, g_kstate);
    cudaGetSymbolAddress((void**)&p_kval, g_kval);
    cudaGetSymbolAddress((void**)&p_nk, g_nk);
    cudaGetSymbolAddress((void**)&p_nv, g_nv);
    cudaGetSymbolAddress((void**)&p_nb, g_nb);
    cudaGetSymbolAddress((void**)&p_ds, g_ds);

    dim3 gemmGrid(32, 32, 4);

    // --- init ---
    ss_kernel<<<1, 256>>>(init_state, 1, nullptr, p_kstate);
    ln_kernel<<<NN, 256>>>(init_val, 0, nullptr, kn_g, kn_b, p_kval);
    ln_kernel<<<NN, 256>>>(p_kval, 0, nullptr, kn_g, kn_b, p_nk);

    // --- transition 1: B -> K ---
    proj_kernel<<<BB * NN / 64, 256>>>(b_val, U_bk, p_sp, BB * NN);
    proj_kernel<<<NN / 64, 256>>>(p_nk, V_bk, p_dp, NN);
    score_gemm_kernel<<<gemmGrid, 256>>>(p_dp, p_sp, p_scores, 1, 0);
    topk_kernel<<<BB * NN, 256>>>(p_scores, p_w, p_idx);
    msg_kernel<<<BB * NN, 256>>>(p_w, p_idx, b_val, 0, b_state,
                                 p_kval, NN, kn_g, kn_b, o_rval, p_ds);
    ss_kernel<<<BB, 256>>>(p_kstate, 1, p_ds, o_rstate);

    // --- propagation ---
    ln_kernel<<<BB * NN, 256>>>(o_rval, 0, nullptr, pn_g, pn_b, p_nv);
    proj_kernel<<<BB * NN / 64, 256>>>(p_nv, U_p, p_sp, BB * NN);
    proj_kernel<<<BB * NN / 64, 256>>>(p_nv, V_p, p_dp, BB * NN);
    score_gemm_kernel<<<gemmGrid, 256>>>(p_dp, p_sp, p_scores, 0, 0);
    topk_kernel<<<BB * NN, 256>>>(p_scores, p_w, p_idx);
    msg_kernel<<<BB * NN, 256>>>(p_w, p_idx, p_nv, 0, nullptr,
                                 o_rval, 0, kn_g, kn_b, o_pval, p_ds);
    ss_kernel<<<BB, 256>>>(o_rstate, 0, p_ds, o_pstate);

    // --- transition 2: K -> B (delta only) ---
    ln_kernel<<<BB * NN, 256>>>(o_pval, 0, nullptr, kn_g, kn_b, p_nv); // nk2
    ln_kernel<<<BB * NN, 256>>>(b_val, 0, nullptr, bn_g, bn_b, p_nb);  // nb
    proj_kernel<<<BB * NN / 64, 256>>>(p_nv, U_kb, p_sp, BB * NN);
    proj_kernel<<<BB * NN / 64, 256>>>(p_nb, V_kb, p_dp, BB * NN);
    score_gemm_kernel<<<gemmGrid, 256>>>(p_dp, p_sp, p_scores, 0, 0);
    topk_kernel<<<BB * NN, 256>>>(p_scores, p_w, p_idx);
    msg_kernel<<<BB * NN, 256>>>(p_w, p_idx, p_nv, 0, o_pstate,
                                 nullptr, 0, nullptr, nullptr, o_bdv, o_bds);
}

// round 4
// speedup vs baseline: 1.3508x; 1.3508x over previous
#include <cuda_runtime.h>
#include <cstdint>
#include <cstddef>

#define BB 4
#define NN 4096
#define DD 256
#define RR 64
#define KK 16

#define FMA2(d, a, b) asm("fma.rn.f32x2 %0, %1, %2, %0;" : "+l"(d) : "l"(a), "l"(b))

// ---------------- device scratch (static; no runtime allocation) ----------------
__device__ float g_scores[(size_t)BB * NN * NN];     // 256 MB
__device__ float g_sp[(size_t)BB * NN * RR];
__device__ float g_dp[(size_t)BB * NN * RR];
__device__ float g_w[(size_t)BB * NN * KK];
__device__ int   g_idx[(size_t)BB * NN * KK];
__device__ float g_kstate[NN];
__device__ float g_kval[(size_t)NN * DD];
__device__ float g_nk[(size_t)NN * DD];
__device__ float g_nv[(size_t)BB * NN * DD];
__device__ float g_nb[(size_t)BB * NN * DD];
__device__ float g_ds[(size_t)BB * NN];

// ---------------- reductions ----------------
__device__ __forceinline__ float warpSum(float v) {
#pragma unroll
    for (int o = 16; o > 0; o >>= 1) v += __shfl_xor_sync(0xffffffffu, v, o);
    return v;
}
__device__ __forceinline__ float warpMax(float v) {
#pragma unroll
    for (int o = 16; o > 0; o >>= 1) v = fmaxf(v, __shfl_xor_sync(0xffffffffu, v, o));
    return v;
}
__device__ __forceinline__ float blockSum256(float v) {
    __shared__ float sh[8];
    int wid = threadIdx.x >> 5, lid = threadIdx.x & 31;
    v = warpSum(v);
    if (lid == 0) sh[wid] = v;
    __syncthreads();
    float r = sh[0] + sh[1] + sh[2] + sh[3] + sh[4] + sh[5] + sh[6] + sh[7];
    __syncthreads();
    return r;
}
__device__ __forceinline__ float blockMax256(float v) {
    __shared__ float sh[8];
    int wid = threadIdx.x >> 5, lid = threadIdx.x & 31;
    v = warpMax(v);
    if (lid == 0) sh[wid] = v;
    __syncthreads();
    float r = fmaxf(fmaxf(fmaxf(sh[0], sh[1]), fmaxf(sh[2], sh[3])),
                    fmaxf(fmaxf(sh[4], sh[5]), fmaxf(sh[6], sh[7])));
    __syncthreads();
    return r;
}

// ---------------- layernorm over rows of 256 ----------------
__global__ void __launch_bounds__(256) ln_kernel(const float* __restrict__ x, int srcMod,
                                                 const float* __restrict__ res,
                                                 const float* __restrict__ g,
                                                 const float* __restrict__ bt,
                                                 float* __restrict__ out) {
    int row = blockIdx.x;
    int srow = srcMod ? (row & (srcMod - 1)) : row;
    int t = threadIdx.x;
    float v = x[(size_t)srow * DD + t];
    if (res) v += res[(size_t)row * DD + t];
    float mean = blockSum256(v) * (1.f / DD);
    float d = v - mean;
    float var = blockSum256(d * d) * (1.f / DD);
    out[(size_t)row * DD + t] = d * rsqrtf(var + 1e-5f) * g[t] + bt[t];
}

// ---------------- signed softmax over rows of 4096 ----------------
__global__ void __launch_bounds__(256) ss_kernel(const float* __restrict__ x, int xB,
                                                 const float* __restrict__ add,
                                                 float* __restrict__ out) {
    int b = blockIdx.x;
    const float* xr = x + (xB ? 0 : (size_t)b * NN);
    const float* ar = add ? add + (size_t)b * NN : nullptr;
    int t = threadIdx.x;
    float v[16];
    float mx = 0.f;
#pragma unroll
    for (int i = 0; i < 16; i++) {
        float u = xr[t + 256 * i];
        if (ar) u += ar[t + 256 * i];
        v[i] = u;
        mx = fmaxf(mx, fabsf(u));
    }
    mx = blockMax256(mx);
    float s = 0.f;
#pragma unroll
    for (int i = 0; i < 16; i++) s += expf(fabsf(v[i]) - mx);
    s = blockSum256(s);
    float inv = 1.f / s;
#pragma unroll
    for (int i = 0; i < 16; i++) {
        float u = v[i];
        float sg = (u > 0.f) ? 1.f : ((u < 0.f) ? -1.f : 0.f);
        out[(size_t)b * NN + t + 256 * i] = sg * expf(fabsf(u) - mx) * inv;
    }
}

// ---------------- projection (round-1 version): X[rows,256] @ W[256,64] ----------------
// 1 thread per (row, 4-col group). occ ~80%, measured 42us.
__global__ void __launch_bounds__(256) proj_kernel(const float* __restrict__ X,
                                                   const float* __restrict__ W,
                                                   float* __restrict__ out, int nrows) {
    int gi = blockIdx.x * 256 + threadIdx.x;
    int row = gi >> 4, cq = gi & 15;
    if (row >= nrows) return;
    const float4* W4 = (const float4*)W;
    const float4* X4 = (const float4*)(X + (size_t)row * DD);
    float4 acc = make_float4(0.f, 0.f, 0.f, 0.f);
#pragma unroll 8
    for (int d4 = 0; d4 < 64; d4++) {
        float4 xv = X4[d4];
        float4 w;
        w = W4[(d4 * 4 + 0) * 16 + cq];
        acc.x = fmaf(xv.x, w.x, acc.x); acc.y = fmaf(xv.x, w.y, acc.y);
        acc.z = fmaf(xv.x, w.z, acc.z); acc.w = fmaf(xv.x, w.w, acc.w);
        w = W4[(d4 * 4 + 1) * 16 + cq];
        acc.x = fmaf(xv.y, w.x, acc.x); acc.y = fmaf(xv.y, w.y, acc.y);
        acc.z = fmaf(xv.y, w.z, acc.z); acc.w = fmaf(xv.y, w.w, acc.w);
        w = W4[(d4 * 4 + 2) * 16 + cq];
        acc.x = fmaf(xv.z, w.x, acc.x); acc.y = fmaf(xv.z, w.y, acc.y);
        acc.z = fmaf(xv.z, w.z, acc.z); acc.w = fmaf(xv.z, w.w, acc.w);
        w = W4[(d4 * 4 + 3) * 16 + cq];
        acc.x = fmaf(xv.w, w.x, acc.x); acc.y = fmaf(xv.w, w.y, acc.y);
        acc.z = fmaf(xv.w, w.z, acc.z); acc.w = fmaf(xv.w, w.w, acc.w);
    }
    ((float4*)out)[(size_t)row * 16 + cq] = acc;
}

// ---------------- score GEMM (round-2 f32x2 version, FMA2-pipe-bound) ----------------
__global__ void __launch_bounds__(256) score_gemm_kernel(const float* __restrict__ dp,
                                                         const float* __restrict__ sp,
                                                         float* __restrict__ out,
                                                         int dpB, int spB) {
    __shared__ float sD[32][132];
    __shared__ float sS[32][132];
    int b = blockIdx.z;
    int n0 = blockIdx.y * 128;
    int m0 = blockIdx.x * 128;
    const float* dpb = dp + (dpB ? 0 : (size_t)b * NN * RR);
    const float* spb = sp + (spB ? 0 : (size_t)b * NN * RR);
    int t = threadIdx.x;
    int tx = t & 15, ty = t >> 4;
    unsigned long long acc[8][4];
#pragma unroll
    for (int i = 0; i < 8; i++)
#pragma unroll
        for (int j = 0; j < 4; j++) acc[i][j] = 0ull;

    for (int kc = 0; kc < 2; kc++) {
        __syncthreads();
#pragma unroll
        for (int i = 0; i < 4; i++) {
            int s = t + i * 256;       // 0..1023
            int r = s >> 3;            // row 0..127
            int kq = s & 7;            // float4 group within 32-k chunk
            float4 dv = *(const float4*)(dpb + (size_t)(n0 + r) * RR + kc * 32 + kq * 4);
            sD[kq * 4 + 0][r] = dv.x; sD[kq * 4 + 1][r] = dv.y;
            sD[kq * 4 + 2][r] = dv.z; sD[kq * 4 + 3][r] = dv.w;
            float4 sv = *(const float4*)(spb + (size_t)(m0 + r) * RR + kc * 32 + kq * 4);
            sS[kq * 4 + 0][r] = sv.x; sS[kq * 4 + 1][r] = sv.y;
            sS[kq * 4 + 2][r] = sv.z; sS[kq * 4 + 3][r] = sv.w;
        }
        __syncthreads();
#pragma unroll 4
        for (int k = 0; k < 32; k++) {
            float4 a0 = *(const float4*)&sD[k][ty * 4];
            float4 a1 = *(const float4*)&sD[k][64 + ty * 4];
            ulonglong2 bq0 = *(const ulonglong2*)&sS[k][tx * 4];
            ulonglong2 bq1 = *(const ulonglong2*)&sS[k][64 + tx * 4];
            unsigned long long bp0 = bq0.x, bp1 = bq0.y, bp2 = bq1.x, bp3 = bq1.y;
            float av[8] = {a0.x, a0.y, a0.z, a0.w, a1.x, a1.y, a1.z, a1.w};
#pragma unroll
            for (int i = 0; i < 8; i++) {
                unsigned long long ad;
                asm("mov.b64 %0, {%1, %1};" : "=l"(ad) : "r"(__float_as_uint(av[i])));
                FMA2(acc[i][0], ad, bp0);
                FMA2(acc[i][1], ad, bp1);
                FMA2(acc[i][2], ad, bp2);
                FMA2(acc[i][3], ad, bp3);
            }
        }
    }
    float* outb = out + ((size_t)b * NN + n0) * NN + m0;
#pragma unroll
    for (int i = 0; i < 8; i++) {
        int n = (i < 4) ? (ty * 4 + i) : (64 + ty * 4 + (i - 4));
        float2 c0 = *(float2*)&acc[i][0];
        float2 c1 = *(float2*)&acc[i][1];
        float2 c2 = *(float2*)&acc[i][2];
        float2 c3 = *(float2*)&acc[i][3];
        float4 r0 = make_float4(c0.x * 0.125f, c0.y * 0.125f, c1.x * 0.125f, c1.y * 0.125f);
        float4 r1 = make_float4(c2.x * 0.125f, c2.y * 0.125f, c3.x * 0.125f, c3.y * 0.125f);
        *(float4*)(outb + (size_t)n * NN + tx * 4) = r0;
        *(float4*)(outb + (size_t)n * NN + 64 + tx * 4) = r1;
    }
}

// ---------------- top-16 by |score| per row: threshold + rank selection ----------------
__global__ void __launch_bounds__(256) topk_kernel(const float* __restrict__ scores,
                                                   float* __restrict__ wOut,
                                                   int* __restrict__ idxOut) {
    __shared__ unsigned int sVal[256];
    __shared__ int sColA[256];
    __shared__ unsigned int warp2[8];
    __shared__ int sCnt;
    size_t row = blockIdx.x;
    const float* sr = scores + row * (size_t)NN;
    int t = threadIdx.x;
    int lid = t & 31, wid = t >> 5;

    float vv[16];
    unsigned int kk[16];
#pragma unroll
    for (int i = 0; i < 4; i++) {
        float4 v = *(const float4*)&sr[t * 4 + i * 1024];
        vv[i * 4 + 0] = v.x; vv[i * 4 + 1] = v.y; vv[i * 4 + 2] = v.z; vv[i * 4 + 3] = v.w;
    }
#pragma unroll
    for (int e = 0; e < 16; e++) kk[e] = __float_as_uint(vv[e]) & 0x7fffffffu;

    unsigned int m1 = 0u, m2 = 0u;
#pragma unroll
    for (int e = 0; e < 16; e++) {
        unsigned int k = kk[e];
        if (k > m1) { m2 = m1; m1 = k; }
        else if (k > m2) { m2 = k; }
    }
#pragma unroll
    for (int o = 16; o > 0; o >>= 1) {
        unsigned int o1 = __shfl_xor_sync(0xffffffffu, m1, o);
        unsigned int o2 = __shfl_xor_sync(0xffffffffu, m2, o);
        if (o1 > m1) { m2 = (m1 > o2) ? m1 : o2; m1 = o1; }
        else { m2 = (m2 > o1) ? m2 : o1; }
    }
    if (lid == 0) warp2[wid] = m2;
    if (t == 0) sCnt = 0;
    __syncthreads();
    unsigned int T = warp2[0];
#pragma unroll
    for (int u = 1; u < 8; u++) T = (warp2[u] < T) ? warp2[u] : T;

#pragma unroll
    for (int e = 0; e < 16; e++) {
        if (kk[e] >= T) {
            int p = atomicAdd(&sCnt, 1);
            if (p < 256) {
                sVal[p] = __float_as_uint(vv[e]);
                sColA[p] = t * 4 + (e & 3) + (e >> 2) * 1024;
            }
        }
    }
    __syncthreads();
    int C = sCnt;
    if (C <= 256) {
        if (t < C) {
            unsigned int vb = sVal[t];
            unsigned int ki = vb & 0x7fffffffu;
            int ci = sColA[t];
            int rank = 0;
            for (int j = 0; j < C; j++) {
                unsigned int vj = sVal[j];
                unsigned int kj = vj & 0x7fffffffu;
                int cj = sColA[j];
                rank += (kj > ki) || (kj == ki && cj < ci);
            }
            if (rank < KK) {
                wOut[row * KK + rank] = __uint_as_float(vb);
                idxOut[row * KK + rank] = ci;
            }
        }
    } else if (t == 0) {
        unsigned int bk[16]; float bv[16]; int bc[16];
        int cnt = 0;
        for (int c = 0; c < NN; c++) {
            float val = sr[c];
            unsigned int key = __float_as_uint(val) & 0x7fffffffu;
            if (cnt == 16 && key <= bk[15]) continue;
            int pos = (cnt < 16) ? cnt : 15;
            while (pos > 0 && bk[pos - 1] < key) {
                bk[pos] = bk[pos - 1]; bv[pos] = bv[pos - 1]; bc[pos] = bc[pos - 1];
                pos--;
            }
            bk[pos] = key; bv[pos] = val; bc[pos] = c;
            if (cnt < 16) cnt++;
        }
        for (int k = 0; k < KK; k++) {
            wOut[row * KK + k] = bv[k];
            idxOut[row * KK + k] = bc[k];
        }
    }
}

// ---------------- fused message aggregation + optional residual layernorm ----------------
__global__ void __launch_bounds__(256) msg_kernel(const float* __restrict__ w,
                                                  const int* __restrict__ idx,
                                                  const float* __restrict__ srcval, int srcB,
                                                  const float* __restrict__ state,
                                                  const float* __restrict__ res, int resMod,
                                                  const float* __restrict__ g,
                                                  const float* __restrict__ bt,
                                                  float* __restrict__ outVal,
                                                  float* __restrict__ dstate) {
    __shared__ float sW[16];
    __shared__ int sI[16];
    __shared__ float sNorm[16];
    size_t row = blockIdx.x;
    int b = (int)(row >> 12);
    int t = threadIdx.x;
    if (t < 16) { sW[t] = w[row * KK + t]; sI[t] = idx[row * KK + t]; }
    __syncthreads();
    if (t == 0) {
        float mx = 0.f;
        for (int k = 0; k < 16; k++) mx = fmaxf(mx, fabsf(sW[k]));
        float e[16];
        float s = 0.f;
        for (int k = 0; k < 16; k++) { e[k] = expf(fabsf(sW[k]) - mx); s += e[k]; }
        float inv = 1.f / s;
        float dsum = 0.f;
        for (int k = 0; k < 16; k++) {
            float u = sW[k];
            float sg = (u > 0.f) ? 1.f : ((u < 0.f) ? -1.f : 0.f);
            float wt = sg * e[k] * inv;
            if (state) {
                float st = state[(size_t)b * NN + sI[k]];
                float sp = fmaxf(st, 0.f) + log1pf(expf(-fabsf(st)));  // softplus
                wt *= sp;
            }
            sW[k] = wt;
            dsum += wt;
        }
        dstate[row] = dsum;
    }
    __syncthreads();
    const float* base = srcval + (srcB ? 0 : (size_t)b * NN * DD);
    int wid = t >> 5, lid = t & 31;
    for (int k = wid; k < 16; k += 8) {
        const float* v = base + (size_t)sI[k] * DD;
        float ss = 0.f;
#pragma unroll
        for (int i = lid; i < 256; i += 32) { float x = v[i]; ss += x * x; }
        ss = warpSum(ss);
        if (lid == 0) sNorm[k] = sqrtf(ss) + 1e-6f;
    }
    __syncthreads();
    float acc = 0.f;
#pragma unroll
    for (int k = 0; k < 16; k++) {
        const float* v = base + (size_t)sI[k] * DD;
        acc = fmaf(sW[k] / sNorm[k], v[t], acc);
    }
    if (g) {
        int srow = resMod ? (int)(row & (resMod - 1)) : (int)row;
        float v = res[(size_t)srow * DD + t] + acc;
        float mean = blockSum256(v) * (1.f / DD);
        float d = v - mean;
        float var = blockSum256(d * d) * (1.f / DD);
        outVal[row * (size_t)DD + t] = d * rsqrtf(var + 1e-5f) * g[t] + bt[t];
    } else {
        outVal[row * (size_t)DD + t] = acc;
    }
}

// ---------------- host orchestration ----------------
extern "C" void kernel_launch(void* const* d_in, const int* in_sizes, int n_in,
                              void* d_out, int out_size) {
    const float* b_state    = (const float*)d_in[0];
    const float* b_val      = (const float*)d_in[1];
    const float* init_state = (const float*)d_in[2];
    const float* init_val   = (const float*)d_in[3];
    const float* U_bk = (const float*)d_in[4];
    const float* V_bk = (const float*)d_in[5];
    const float* U_kb = (const float*)d_in[6];
    const float* V_kb = (const float*)d_in[7];
    const float* U_p  = (const float*)d_in[8];
    const float* V_p  = (const float*)d_in[9];
    const float* kn_g = (const float*)d_in[10];
    const float* kn_b = (const float*)d_in[11];
    const float* bn_g = (const float*)d_in[12];
    const float* bn_b = (const float*)d_in[13];
    const float* pn_g = (const float*)d_in[14];
    const float* pn_b = (const float*)d_in[15];

    float* out = (float*)d_out;
    float* o_rstate = out;
    float* o_rval   = o_rstate + (size_t)BB * NN;
    float* o_pstate = o_rval + (size_t)BB * NN * DD;
    float* o_pval   = o_pstate + (size_t)BB * NN;
    float* o_bds    = o_pval + (size_t)BB * NN * DD;
    float* o_bdv    = o_bds + (size_t)BB * NN;

    float *p_scores, *p_sp, *p_dp, *p_w, *p_kstate, *p_kval, *p_nk, *p_nv, *p_nb, *p_ds;
    int* p_idx;
    cudaGetSymbolAddress((void**)&p_scores, g_scores);
    cudaGetSymbolAddress((void**)&p_sp, g_sp);
    cudaGetSymbolAddress((void**)&p_dp, g_dp);
    cudaGetSymbolAddress((void**)&p_w, g_w);
    cudaGetSymbolAddress((void**)&p_idx, g_idx);
    cudaGetSymbolAddress((void**)&p_kstate, g_kstate);
    cudaGetSymbolAddress((void**)&p_kval, g_kval);
    cudaGetSymbolAddress((void**)&p_nk, g_nk);
    cudaGetSymbolAddress((void**)&p_nv, g_nv);
    cudaGetSymbolAddress((void**)&p_nb, g_nb);
    cudaGetSymbolAddress((void**)&p_ds, g_ds);

    dim3 gemmGrid(32, 32, 4);

    // --- init ---
    ss_kernel<<<1, 256>>>(init_state, 1, nullptr, p_kstate);
    ln_kernel<<<NN, 256>>>(init_val, 0, nullptr, kn_g, kn_b, p_kval);
    ln_kernel<<<NN, 256>>>(p_kval, 0, nullptr, kn_g, kn_b, p_nk);

    // --- transition 1: B -> K ---
    proj_kernel<<<(BB * NN * 16) / 256, 256>>>(b_val, U_bk, p_sp, BB * NN);
    proj_kernel<<<(NN * 16) / 256, 256>>>(p_nk, V_bk, p_dp, NN);
    score_gemm_kernel<<<gemmGrid, 256>>>(p_dp, p_sp, p_scores, 1, 0);
    topk_kernel<<<BB * NN, 256>>>(p_scores, p_w, p_idx);
    msg_kernel<<<BB * NN, 256>>>(p_w, p_idx, b_val, 0, b_state,
                                 p_kval, NN, kn_g, kn_b, o_rval, p_ds);
    ss_kernel<<<BB, 256>>>(p_kstate, 1, p_ds, o_rstate);

    // --- propagation ---
    ln_kernel<<<BB * NN, 256>>>(o_rval, 0, nullptr, pn_g, pn_b, p_nv);
    proj_kernel<<<(BB * NN * 16) / 256, 256>>>(p_nv, U_p, p_sp, BB * NN);
    proj_kernel<<<(BB * NN * 16) / 256, 256>>>(p_nv, V_p, p_dp, BB * NN);
    score_gemm_kernel<<<gemmGrid, 256>>>(p_dp, p_sp, p_scores, 0, 0);
    topk_kernel<<<BB * NN, 256>>>(p_scores, p_w, p_idx);
    msg_kernel<<<BB * NN, 256>>>(p_w, p_idx, p_nv, 0, nullptr,
                                 o_rval, 0, kn_g, kn_b, o_pval, p_ds);
    ss_kernel<<<BB, 256>>>(o_rstate, 0, p_ds, o_pstate);

    // --- transition 2: K -> B (delta only) ---
    ln_kernel<<<BB * NN, 256>>>(o_pval, 0, nullptr, kn_g, kn_b, p_nv); // nk2
    ln_kernel<<<BB * NN, 256>>>(b_val, 0, nullptr, bn_g, bn_b, p_nb);  // nb
    proj_kernel<<<(BB * NN * 16) / 256, 256>>>(p_nv, U_kb, p_sp, BB * NN);
    proj_kernel<<<(BB * NN * 16) / 256, 256>>>(p_nb, V_kb, p_dp, BB * NN);
    score_gemm_kernel<<<gemmGrid, 256>>>(p_dp, p_sp, p_scores, 0, 0);
    topk_kernel<<<BB * NN, 256>>>(p_scores, p_w, p_idx);
    msg_kernel<<<BB * NN, 256>>>(p_w, p_idx, p_nv, 0, o_pstate,
                                 nullptr, 0, nullptr, nullptr, o_bdv, o_bds);
}